// round 3
// baseline (speedup 1.0000x reference)
#include <cuda_runtime.h>
#include <cuda_bf16.h>
#include <math.h>

#define N_NODES 100000
#define N_EDGES 1600000
#define N_GRAPHS 2000
#define IN_C 9
#define HID 256
#define OUTF 128
#define BN_EPS 1e-5f

// ---------------- scratch (device globals; allocation-free rule) ----------------
__device__ float g_dinv[N_NODES];
__device__ int   g_cnt[N_NODES];          // degree counts, reused as fill cursors
__device__ int   g_rowptr[N_NODES + 1];
__device__ int   g_csr_src[N_EDGES];
__device__ float g_csr_w[N_EDGES];        // dinv[src] per CSR slot
__device__ float g_xa[N_NODES * IN_C];    // aggregated input features
__device__ __align__(16) float g_h1[N_NODES * HID];   // layer-1 pre-BN output
__device__ __align__(16) float g_z [N_NODES * OUTF];  // bnrelu(h1) @ W2
__device__ __align__(16) float g_h2[N_NODES * OUTF];  // aggregated layer-2 output (+b2)
__device__ float g_stat1[2 * HID];        // sums, sumsq
__device__ float g_stat2[2 * OUTF];
__device__ float g_sc1[HID], g_sh1[HID];  // BN1 fused affine
__device__ float g_sc2[OUTF], g_sh2[OUTF];
__device__ int   g_gstart[N_GRAPHS + 1];

// ---------------- kernels ----------------

__global__ void k_init() {
    int i = blockIdx.x * blockDim.x + threadIdx.x;
    if (i < N_NODES) g_cnt[i] = 0;
    if (i < 2 * HID) g_stat1[i] = 0.f;
    if (i < 2 * OUTF) g_stat2[i] = 0.f;
}

__global__ void k_count(const int* __restrict__ edge) {
    int e = blockIdx.x * blockDim.x + threadIdx.x;
    if (e >= N_EDGES) return;
    int dst = edge[N_EDGES + e];
    atomicAdd(&g_cnt[dst], 1);
}

__global__ void k_dinv() {
    int i = blockIdx.x * blockDim.x + threadIdx.x;
    if (i >= N_NODES) return;
    g_dinv[i] = rsqrtf((float)(g_cnt[i] + 1));   // +1 self-loop
}

// single-block exclusive scan of g_cnt -> g_rowptr; zeros g_cnt for fill phase
__global__ void k_scan() {
    __shared__ int sh[1024];
    const int t = threadIdx.x;
    const int CH = (N_NODES + 1023) / 1024;
    const int base = t * CH;
    int sum = 0;
    for (int i = 0; i < CH; i++) {
        int idx = base + i;
        if (idx < N_NODES) sum += g_cnt[idx];
    }
    sh[t] = sum;
    __syncthreads();
    for (int off = 1; off < 1024; off <<= 1) {
        int v = sh[t];
        int add = (t >= off) ? sh[t - off] : 0;
        __syncthreads();
        sh[t] = v + add;
        __syncthreads();
    }
    int prefix = (t == 0) ? 0 : sh[t - 1];
    for (int i = 0; i < CH; i++) {
        int idx = base + i;
        if (idx < N_NODES) {
            int c = g_cnt[idx];
            g_rowptr[idx] = prefix;
            prefix += c;
            g_cnt[idx] = 0;
        }
    }
    if (t == 0) g_rowptr[N_NODES] = N_EDGES;
}

__global__ void k_fill(const int* __restrict__ edge) {
    int e = blockIdx.x * blockDim.x + threadIdx.x;
    if (e >= N_EDGES) return;
    int s = edge[e];
    int d = edge[N_EDGES + e];
    int p = g_rowptr[d] + atomicAdd(&g_cnt[d], 1);
    g_csr_src[p] = s;
    g_csr_w[p] = g_dinv[s];
}

// aggregate raw input features (width 9): xa[n] = dinv[n]*sum + dinv[n]^2*x[n]
__global__ void k_agg1(const float* __restrict__ x) {
    int n = blockIdx.x * blockDim.x + threadIdx.x;
    if (n >= N_NODES) return;
    float acc[IN_C];
#pragma unroll
    for (int k = 0; k < IN_C; k++) acc[k] = 0.f;
    int s = g_rowptr[n], e = g_rowptr[n + 1];
    for (int p = s; p < e; p++) {
        int sn = g_csr_src[p];
        float w = g_csr_w[p];
        const float* xr = x + (long)sn * IN_C;
#pragma unroll
        for (int k = 0; k < IN_C; k++) acc[k] += w * xr[k];
    }
    float dn = g_dinv[n];
    float d2 = dn * dn;
    const float* xn = x + (long)n * IN_C;
#pragma unroll
    for (int k = 0; k < IN_C; k++) g_xa[n * IN_C + k] = dn * acc[k] + d2 * xn[k];
}

// h1 = xa @ W1 + b1, fused BN1 stats (64 rows per block, thread = column)
#define G1_ROWS 64
__global__ __launch_bounds__(256) void k_gemm1(const float* __restrict__ W1,
                                               const float* __restrict__ b1) {
    __shared__ float W1s[IN_C * HID];
    __shared__ float xas[G1_ROWS * IN_C];
    int t = threadIdx.x;
    int row0 = blockIdx.x * G1_ROWS;
    for (int i = t; i < IN_C * HID; i += 256) W1s[i] = W1[i];
    for (int i = t; i < G1_ROWS * IN_C; i += 256) {
        int r = row0 + i / IN_C;
        xas[i] = (r < N_NODES) ? g_xa[(long)r * IN_C + (i % IN_C)] : 0.f;
    }
    __syncthreads();
    float b1j = b1[t];
    float sum = 0.f, sq = 0.f;
    for (int r = 0; r < G1_ROWS; r++) {
        int row = row0 + r;
        if (row >= N_NODES) break;
        float h = b1j;
#pragma unroll
        for (int k = 0; k < IN_C; k++) h += xas[r * IN_C + k] * W1s[k * HID + t];
        g_h1[(long)row * HID + t] = h;
        sum += h;
        sq += h * h;
    }
    atomicAdd(&g_stat1[t], sum);
    atomicAdd(&g_stat1[HID + t], sq);
}

__global__ void k_bn1(const float* __restrict__ g1, const float* __restrict__ be1) {
    int j = threadIdx.x;
    float mean = g_stat1[j] / (float)N_NODES;
    float var = g_stat1[HID + j] / (float)N_NODES - mean * mean;
    var = fmaxf(var, 0.f);
    float sc = rsqrtf(var + BN_EPS) * g1[j];
    g_sc1[j] = sc;
    g_sh1[j] = be1[j] - mean * sc;
}

// z = relu(bn1(h1)) @ W2    [100k x 256] @ [256 x 128], fp32 tiled SGEMM
// BM=64, BN=128(full), BK=32, 256 threads, thread computes 8x4
#define BM 64
#define BK 32
__global__ __launch_bounds__(256) void k_gemm2(const float* __restrict__ W2) {
    __shared__ __align__(16) float As[BK * 65];   // padded stride 65
    __shared__ __align__(16) float Bs[BK * OUTF];
    __shared__ float s1s[HID], t1s[HID];
    int t = threadIdx.x;
    int row0 = blockIdx.x * BM;
    int tx = t & 31, ty = t >> 5;
    for (int i = t; i < HID; i += 256) { s1s[i] = g_sc1[i]; t1s[i] = g_sh1[i]; }
    float acc[8][4];
#pragma unroll
    for (int j = 0; j < 8; j++)
#pragma unroll
        for (int i = 0; i < 4; i++) acc[j][i] = 0.f;
    __syncthreads();

    for (int kt = 0; kt < HID / BK; kt++) {
        // load A tile (with BN+relu applied), store transposed [kk][row]
#pragma unroll
        for (int q0 = 0; q0 < 2; q0++) {
            int q = t + q0 * 256;
            int row = q >> 3;            // 0..63
            int a4 = q & 7;              // float4 index within the 32-wide k chunk
            int kloc = a4 * 4;
            int kg = kt * BK + kloc;
            int grow = row0 + row;
            float4 v = make_float4(0.f, 0.f, 0.f, 0.f);
            if (grow < N_NODES)
                v = *reinterpret_cast<const float4*>(&g_h1[(long)grow * HID + kg]);
            float e0 = fmaxf(v.x * s1s[kg + 0] + t1s[kg + 0], 0.f);
            float e1 = fmaxf(v.y * s1s[kg + 1] + t1s[kg + 1], 0.f);
            float e2 = fmaxf(v.z * s1s[kg + 2] + t1s[kg + 2], 0.f);
            float e3 = fmaxf(v.w * s1s[kg + 3] + t1s[kg + 3], 0.f);
            As[(kloc + 0) * 65 + row] = e0;
            As[(kloc + 1) * 65 + row] = e1;
            As[(kloc + 2) * 65 + row] = e2;
            As[(kloc + 3) * 65 + row] = e3;
        }
        // load B tile [kk][col]
#pragma unroll
        for (int i = 0; i < 4; i++) {
            int q = t + i * 256;
            int kb = q >> 5;
            int col4 = (q & 31) * 4;
            *reinterpret_cast<float4*>(&Bs[kb * OUTF + col4]) =
                *reinterpret_cast<const float4*>(&W2[(long)(kt * BK + kb) * OUTF + col4]);
        }
        __syncthreads();
#pragma unroll
        for (int kk = 0; kk < BK; kk++) {
            float4 b = *reinterpret_cast<const float4*>(&Bs[kk * OUTF + tx * 4]);
            float a[8];
#pragma unroll
            for (int j = 0; j < 8; j++) a[j] = As[kk * 65 + ty * 8 + j];
#pragma unroll
            for (int j = 0; j < 8; j++) {
                acc[j][0] += a[j] * b.x;
                acc[j][1] += a[j] * b.y;
                acc[j][2] += a[j] * b.z;
                acc[j][3] += a[j] * b.w;
            }
        }
        __syncthreads();
    }
#pragma unroll
    for (int j = 0; j < 8; j++) {
        int row = row0 + ty * 8 + j;
        if (row < N_NODES) {
            float4 v = make_float4(acc[j][0], acc[j][1], acc[j][2], acc[j][3]);
            *reinterpret_cast<float4*>(&g_z[(long)row * OUTF + tx * 4]) = v;
        }
    }
}

// aggregate z (width 128), add b2, fused BN2 stats. 128 threads, 8 nodes/block.
#define A2_NPB 8
__global__ __launch_bounds__(128) void k_agg2(const float* __restrict__ b2) {
    int j = threadIdx.x;
    int n0 = blockIdx.x * A2_NPB;
    float b2j = b2[j];
    float bs = 0.f, bq = 0.f;
#pragma unroll 1
    for (int u = 0; u < A2_NPB; u++) {
        int n = n0 + u;
        int s = g_rowptr[n], e = g_rowptr[n + 1];
        float acc = 0.f;
        for (int p = s; p < e; p++) {
            int sn = g_csr_src[p];
            float w = g_csr_w[p];
            acc += w * g_z[(long)sn * OUTF + j];
        }
        float dn = g_dinv[n];
        float val = dn * acc + dn * dn * g_z[(long)n * OUTF + j] + b2j;
        g_h2[(long)n * OUTF + j] = val;
        bs += val;
        bq += val * val;
    }
    atomicAdd(&g_stat2[j], bs);
    atomicAdd(&g_stat2[OUTF + j], bq);
}

__global__ void k_bn2(const float* __restrict__ g2, const float* __restrict__ be2) {
    int j = threadIdx.x;
    float mean = g_stat2[j] / (float)N_NODES;
    float var = g_stat2[OUTF + j] / (float)N_NODES - mean * mean;
    var = fmaxf(var, 0.f);
    float sc = rsqrtf(var + BN_EPS) * g2[j];
    g_sc2[j] = sc;
    g_sh2[j] = be2[j] - mean * sc;
}

// graph start offsets (batch is sorted)
__global__ void k_gstart(const int* __restrict__ batch) {
    int i = blockIdx.x * blockDim.x + threadIdx.x;
    if (i > N_NODES) return;
    int b = (i < N_NODES) ? batch[i] : N_GRAPHS;
    int bp = (i > 0) ? batch[i - 1] : -1;
    for (int g = bp + 1; g <= b && g <= N_GRAPHS; g++) g_gstart[g] = i;
}

// per-graph mean pool, BN2 affine, L2 normalize
__global__ __launch_bounds__(128) void k_pool(float* __restrict__ out) {
    int g = blockIdx.x;
    int j = threadIdx.x;
    int s = g_gstart[g], e = g_gstart[g + 1];
    float acc = 0.f;
    for (int i = s; i < e; i++) acc += g_h2[(long)i * OUTF + j];
    int cnt = e - s;
    float y = 0.f;
    if (cnt > 0) {
        float p = acc / (float)cnt;
        y = p * g_sc2[j] + g_sh2[j];
    }
    float v = y * y;
#pragma unroll
    for (int off = 16; off > 0; off >>= 1) v += __shfl_xor_sync(0xffffffffu, v, off);
    __shared__ float ws[4];
    if ((j & 31) == 0) ws[j >> 5] = v;
    __syncthreads();
    float ss = ws[0] + ws[1] + ws[2] + ws[3];
    float nrm = sqrtf(ss);
    out[g * OUTF + j] = y / fmaxf(nrm, 1e-12f);
}

// ---------------- launch ----------------
extern "C" void kernel_launch(void* const* d_in, const int* in_sizes, int n_in,
                              void* d_out, int out_size) {
    const float* x   = (const float*)d_in[0];
    const float* W1  = (const float*)d_in[1];
    const float* b1  = (const float*)d_in[2];
    const float* g1  = (const float*)d_in[3];
    const float* be1 = (const float*)d_in[4];
    const float* W2  = (const float*)d_in[5];
    const float* b2  = (const float*)d_in[6];
    const float* g2  = (const float*)d_in[7];
    const float* be2 = (const float*)d_in[8];
    const int* edge  = (const int*)d_in[9];
    const int* batch = (const int*)d_in[10];
    float* out = (float*)d_out;

    const int TB = 256;
    int nb_N = (N_NODES + TB - 1) / TB;
    int nb_E = (N_EDGES + TB - 1) / TB;
    int nb_gemm = (N_NODES + BM - 1) / BM;

    k_init<<<nb_N, TB>>>();
    k_count<<<nb_E, TB>>>(edge);
    k_dinv<<<nb_N, TB>>>();
    k_scan<<<1, 1024>>>();
    k_fill<<<nb_E, TB>>>(edge);
    k_agg1<<<nb_N, TB>>>(x);
    k_gemm1<<<(N_NODES + G1_ROWS - 1) / G1_ROWS, 256>>>(W1, b1);
    k_bn1<<<1, HID>>>(g1, be1);
    k_gemm2<<<nb_gemm, 256>>>(W2);
    k_agg2<<<N_NODES / A2_NPB, 128>>>(b2);
    k_bn2<<<1, OUTF>>>(g2, be2);
    k_gstart<<<(N_NODES + 1 + TB - 1) / TB, TB>>>(batch);
    k_pool<<<N_GRAPHS, 128>>>(out);
}

// round 4
// speedup vs baseline: 1.3002x; 1.3002x over previous
#include <cuda_runtime.h>
#include <cuda_bf16.h>
#include <math.h>

#define N_NODES 100000
#define N_EDGES 1600000
#define N_GRAPHS 2000
#define IN_C 9
#define HID 256
#define OUTF 128
#define BN_EPS 1e-5f

#define SCAN_B 1024
#define SCAN_NB ((N_NODES + SCAN_B - 1) / SCAN_B)   // 98

// ---------------- scratch (device globals; allocation-free rule) ----------------
__device__ float g_dinv[N_NODES];
__device__ int   g_cnt[N_NODES];          // degree counts, reused as fill cursors
__device__ int   g_rowptr[N_NODES + 1];
__device__ int   g_bsum[SCAN_NB];
__device__ int   g_csr_src[N_EDGES];
__device__ float g_csr_w[N_EDGES];        // dinv[src] per CSR slot
__device__ float g_xa[N_NODES * IN_C];    // aggregated input features
__device__ __align__(16) float g_h1[N_NODES * HID];   // layer-1 pre-BN output
__device__ __align__(16) float g_z [N_NODES * OUTF];  // bnrelu(h1) @ W2
__device__ __align__(16) float g_h2[N_NODES * OUTF];  // aggregated layer-2 output (+b2)
__device__ float g_stat1[2 * HID];        // sums, sumsq
__device__ float g_stat2[2 * OUTF];
__device__ float g_sc1[HID], g_sh1[HID];  // BN1 fused affine
__device__ float g_sc2[OUTF], g_sh2[OUTF];
__device__ int   g_gstart[N_GRAPHS + 1];

// ---------------- kernels ----------------

__global__ void k_init() {
    int i = blockIdx.x * blockDim.x + threadIdx.x;
    if (i < N_NODES) g_cnt[i] = 0;
    if (i < 2 * HID) g_stat1[i] = 0.f;
    if (i < 2 * OUTF) g_stat2[i] = 0.f;
}

__global__ void k_count(const int* __restrict__ edge) {
    int e = blockIdx.x * blockDim.x + threadIdx.x;
    if (e >= N_EDGES) return;
    int dst = edge[N_EDGES + e];
    atomicAdd(&g_cnt[dst], 1);
}

// phase 1: per-block exclusive scan of g_cnt into g_rowptr (local), block totals
// to g_bsum; also computes g_dinv from the counts.
__global__ __launch_bounds__(SCAN_B) void k_scan1() {
    __shared__ int sh[SCAN_B];
    int t = threadIdx.x;
    int i = blockIdx.x * SCAN_B + t;
    int c = (i < N_NODES) ? g_cnt[i] : 0;
    if (i < N_NODES) g_dinv[i] = rsqrtf((float)(c + 1));   // +1 self-loop
    sh[t] = c;
    __syncthreads();
#pragma unroll
    for (int off = 1; off < SCAN_B; off <<= 1) {
        int v = sh[t];
        int add = (t >= off) ? sh[t - off] : 0;
        __syncthreads();
        sh[t] = v + add;
        __syncthreads();
    }
    if (i < N_NODES) g_rowptr[i] = sh[t] - c;    // exclusive local prefix
    if (t == SCAN_B - 1) g_bsum[blockIdx.x] = sh[t];
}

// phase 2: exclusive scan over the 98 block sums (single small block)
__global__ void k_scan2() {
    __shared__ int sh[128];
    int t = threadIdx.x;
    int v = (t < SCAN_NB) ? g_bsum[t] : 0;
    sh[t] = v;
    __syncthreads();
#pragma unroll
    for (int off = 1; off < 128; off <<= 1) {
        int x = sh[t];
        int add = (t >= off) ? sh[t - off] : 0;
        __syncthreads();
        sh[t] = x + add;
        __syncthreads();
    }
    if (t < SCAN_NB) g_bsum[t] = sh[t] - v;      // exclusive
}

// phase 3: add block offsets, zero g_cnt for the fill pass
__global__ __launch_bounds__(SCAN_B) void k_scan3() {
    int i = blockIdx.x * SCAN_B + threadIdx.x;
    if (i < N_NODES) {
        g_rowptr[i] += g_bsum[blockIdx.x];
        g_cnt[i] = 0;
    }
    if (i == 0) g_rowptr[N_NODES] = N_EDGES;
}

__global__ void k_fill(const int* __restrict__ edge) {
    int e = blockIdx.x * blockDim.x + threadIdx.x;
    if (e >= N_EDGES) return;
    int s = edge[e];
    int d = edge[N_EDGES + e];
    int p = g_rowptr[d] + atomicAdd(&g_cnt[d], 1);
    g_csr_src[p] = s;
    g_csr_w[p] = g_dinv[s];
}

// aggregate raw input features (width 9): xa[n] = dinv[n]*sum + dinv[n]^2*x[n]
__global__ void k_agg1(const float* __restrict__ x) {
    int n = blockIdx.x * blockDim.x + threadIdx.x;
    if (n >= N_NODES) return;
    float acc[IN_C];
#pragma unroll
    for (int k = 0; k < IN_C; k++) acc[k] = 0.f;
    int s = g_rowptr[n], e = g_rowptr[n + 1];
    for (int p = s; p < e; p++) {
        int sn = g_csr_src[p];
        float w = g_csr_w[p];
        const float* xr = x + (long)sn * IN_C;
#pragma unroll
        for (int k = 0; k < IN_C; k++) acc[k] += w * xr[k];
    }
    float dn = g_dinv[n];
    float d2 = dn * dn;
    const float* xn = x + (long)n * IN_C;
#pragma unroll
    for (int k = 0; k < IN_C; k++) g_xa[n * IN_C + k] = dn * acc[k] + d2 * xn[k];
}

// h1 = xa @ W1 + b1, fused BN1 stats (64 rows per block, thread = column)
#define G1_ROWS 64
__global__ __launch_bounds__(256) void k_gemm1(const float* __restrict__ W1,
                                               const float* __restrict__ b1) {
    __shared__ float W1s[IN_C * HID];
    __shared__ float xas[G1_ROWS * IN_C];
    int t = threadIdx.x;
    int row0 = blockIdx.x * G1_ROWS;
    for (int i = t; i < IN_C * HID; i += 256) W1s[i] = W1[i];
    for (int i = t; i < G1_ROWS * IN_C; i += 256) {
        int r = row0 + i / IN_C;
        xas[i] = (r < N_NODES) ? g_xa[(long)r * IN_C + (i % IN_C)] : 0.f;
    }
    __syncthreads();
    float b1j = b1[t];
    float sum = 0.f, sq = 0.f;
    for (int r = 0; r < G1_ROWS; r++) {
        int row = row0 + r;
        if (row >= N_NODES) break;
        float h = b1j;
#pragma unroll
        for (int k = 0; k < IN_C; k++) h += xas[r * IN_C + k] * W1s[k * HID + t];
        g_h1[(long)row * HID + t] = h;
        sum += h;
        sq += h * h;
    }
    atomicAdd(&g_stat1[t], sum);
    atomicAdd(&g_stat1[HID + t], sq);
}

__global__ void k_bn1(const float* __restrict__ g1, const float* __restrict__ be1) {
    int j = threadIdx.x;
    float mean = g_stat1[j] / (float)N_NODES;
    float var = g_stat1[HID + j] / (float)N_NODES - mean * mean;
    var = fmaxf(var, 0.f);
    float sc = rsqrtf(var + BN_EPS) * g1[j];
    g_sc1[j] = sc;
    g_sh1[j] = be1[j] - mean * sc;
}

// z = relu(bn1(h1)) @ W2    [100k x 256] @ [256 x 128], fp32 tiled SGEMM
// BM=64, BN=128(full), BK=32, 256 threads, thread computes 8x4
#define BM 64
#define BK 32
__global__ __launch_bounds__(256) void k_gemm2(const float* __restrict__ W2) {
    __shared__ __align__(16) float As[BK * 65];   // padded stride 65
    __shared__ __align__(16) float Bs[BK * OUTF];
    __shared__ float s1s[HID], t1s[HID];
    int t = threadIdx.x;
    int row0 = blockIdx.x * BM;
    int tx = t & 31, ty = t >> 5;
    for (int i = t; i < HID; i += 256) { s1s[i] = g_sc1[i]; t1s[i] = g_sh1[i]; }
    float acc[8][4];
#pragma unroll
    for (int j = 0; j < 8; j++)
#pragma unroll
        for (int i = 0; i < 4; i++) acc[j][i] = 0.f;
    __syncthreads();

    for (int kt = 0; kt < HID / BK; kt++) {
        // load A tile (with BN+relu applied), store transposed [kk][row]
#pragma unroll
        for (int q0 = 0; q0 < 2; q0++) {
            int q = t + q0 * 256;
            int row = q >> 3;            // 0..63
            int a4 = q & 7;              // float4 index within the 32-wide k chunk
            int kloc = a4 * 4;
            int kg = kt * BK + kloc;
            int grow = row0 + row;
            float4 v = make_float4(0.f, 0.f, 0.f, 0.f);
            if (grow < N_NODES)
                v = *reinterpret_cast<const float4*>(&g_h1[(long)grow * HID + kg]);
            float e0 = fmaxf(v.x * s1s[kg + 0] + t1s[kg + 0], 0.f);
            float e1 = fmaxf(v.y * s1s[kg + 1] + t1s[kg + 1], 0.f);
            float e2 = fmaxf(v.z * s1s[kg + 2] + t1s[kg + 2], 0.f);
            float e3 = fmaxf(v.w * s1s[kg + 3] + t1s[kg + 3], 0.f);
            As[(kloc + 0) * 65 + row] = e0;
            As[(kloc + 1) * 65 + row] = e1;
            As[(kloc + 2) * 65 + row] = e2;
            As[(kloc + 3) * 65 + row] = e3;
        }
        // load B tile [kk][col]
#pragma unroll
        for (int i = 0; i < 4; i++) {
            int q = t + i * 256;
            int kb = q >> 5;
            int col4 = (q & 31) * 4;
            *reinterpret_cast<float4*>(&Bs[kb * OUTF + col4]) =
                *reinterpret_cast<const float4*>(&W2[(long)(kt * BK + kb) * OUTF + col4]);
        }
        __syncthreads();
#pragma unroll
        for (int kk = 0; kk < BK; kk++) {
            float4 b = *reinterpret_cast<const float4*>(&Bs[kk * OUTF + tx * 4]);
            float a[8];
#pragma unroll
            for (int j = 0; j < 8; j++) a[j] = As[kk * 65 + ty * 8 + j];
#pragma unroll
            for (int j = 0; j < 8; j++) {
                acc[j][0] += a[j] * b.x;
                acc[j][1] += a[j] * b.y;
                acc[j][2] += a[j] * b.z;
                acc[j][3] += a[j] * b.w;
            }
        }
        __syncthreads();
    }
#pragma unroll
    for (int j = 0; j < 8; j++) {
        int row = row0 + ty * 8 + j;
        if (row < N_NODES) {
            float4 v = make_float4(acc[j][0], acc[j][1], acc[j][2], acc[j][3]);
            *reinterpret_cast<float4*>(&g_z[(long)row * OUTF + tx * 4]) = v;
        }
    }
}

// aggregate z (width 128), add b2, fused BN2 stats. 128 threads, 8 nodes/block.
#define A2_NPB 8
__global__ __launch_bounds__(128) void k_agg2(const float* __restrict__ b2) {
    int j = threadIdx.x;
    int n0 = blockIdx.x * A2_NPB;
    float b2j = b2[j];
    float bs = 0.f, bq = 0.f;
#pragma unroll 1
    for (int u = 0; u < A2_NPB; u++) {
        int n = n0 + u;
        int s = g_rowptr[n], e = g_rowptr[n + 1];
        float acc = 0.f;
        for (int p = s; p < e; p++) {
            int sn = g_csr_src[p];
            float w = g_csr_w[p];
            acc += w * g_z[(long)sn * OUTF + j];
        }
        float dn = g_dinv[n];
        float val = dn * acc + dn * dn * g_z[(long)n * OUTF + j] + b2j;
        g_h2[(long)n * OUTF + j] = val;
        bs += val;
        bq += val * val;
    }
    atomicAdd(&g_stat2[j], bs);
    atomicAdd(&g_stat2[OUTF + j], bq);
}

__global__ void k_bn2(const float* __restrict__ g2, const float* __restrict__ be2) {
    int j = threadIdx.x;
    float mean = g_stat2[j] / (float)N_NODES;
    float var = g_stat2[OUTF + j] / (float)N_NODES - mean * mean;
    var = fmaxf(var, 0.f);
    float sc = rsqrtf(var + BN_EPS) * g2[j];
    g_sc2[j] = sc;
    g_sh2[j] = be2[j] - mean * sc;
}

// graph start offsets (batch is sorted)
__global__ void k_gstart(const int* __restrict__ batch) {
    int i = blockIdx.x * blockDim.x + threadIdx.x;
    if (i > N_NODES) return;
    int b = (i < N_NODES) ? batch[i] : N_GRAPHS;
    int bp = (i > 0) ? batch[i - 1] : -1;
    for (int g = bp + 1; g <= b && g <= N_GRAPHS; g++) g_gstart[g] = i;
}

// per-graph mean pool, BN2 affine, L2 normalize
__global__ __launch_bounds__(128) void k_pool(float* __restrict__ out) {
    int g = blockIdx.x;
    int j = threadIdx.x;
    int s = g_gstart[g], e = g_gstart[g + 1];
    float acc = 0.f;
    for (int i = s; i < e; i++) acc += g_h2[(long)i * OUTF + j];
    int cnt = e - s;
    float y = 0.f;
    if (cnt > 0) {
        float p = acc / (float)cnt;
        y = p * g_sc2[j] + g_sh2[j];
    }
    float v = y * y;
#pragma unroll
    for (int off = 16; off > 0; off >>= 1) v += __shfl_xor_sync(0xffffffffu, v, off);
    __shared__ float ws[4];
    if ((j & 31) == 0) ws[j >> 5] = v;
    __syncthreads();
    float ss = ws[0] + ws[1] + ws[2] + ws[3];
    float nrm = sqrtf(ss);
    out[g * OUTF + j] = y / fmaxf(nrm, 1e-12f);
}

// ---------------- launch ----------------
extern "C" void kernel_launch(void* const* d_in, const int* in_sizes, int n_in,
                              void* d_out, int out_size) {
    const float* x   = (const float*)d_in[0];
    const float* W1  = (const float*)d_in[1];
    const float* b1  = (const float*)d_in[2];
    const float* g1  = (const float*)d_in[3];
    const float* be1 = (const float*)d_in[4];
    const float* W2  = (const float*)d_in[5];
    const float* b2  = (const float*)d_in[6];
    const float* g2  = (const float*)d_in[7];
    const float* be2 = (const float*)d_in[8];
    const int* edge  = (const int*)d_in[9];
    const int* batch = (const int*)d_in[10];
    float* out = (float*)d_out;

    const int TB = 256;
    int nb_N = (N_NODES + TB - 1) / TB;
    int nb_E = (N_EDGES + TB - 1) / TB;
    int nb_gemm = (N_NODES + BM - 1) / BM;

    k_init<<<nb_N, TB>>>();
    k_count<<<nb_E, TB>>>(edge);
    k_scan1<<<SCAN_NB, SCAN_B>>>();
    k_scan2<<<1, 128>>>();
    k_scan3<<<SCAN_NB, SCAN_B>>>();
    k_fill<<<nb_E, TB>>>(edge);
    k_agg1<<<nb_N, TB>>>(x);
    k_gemm1<<<(N_NODES + G1_ROWS - 1) / G1_ROWS, 256>>>(W1, b1);
    k_bn1<<<1, HID>>>(g1, be1);
    k_gemm2<<<nb_gemm, 256>>>(W2);
    k_agg2<<<N_NODES / A2_NPB, 128>>>(b2);
    k_bn2<<<1, OUTF>>>(g2, be2);
    k_gstart<<<(N_NODES + 1 + TB - 1) / TB, TB>>>(batch);
    k_pool<<<N_GRAPHS, 128>>>(out);
}

// round 5
// speedup vs baseline: 1.6067x; 1.2357x over previous
#include <cuda_runtime.h>
#include <cuda_bf16.h>
#include <math.h>

#define N_NODES 100000
#define N_EDGES 1600000
#define N_GRAPHS 2000
#define IN_C 9
#define HID 256
#define OUTF 128
#define BN_EPS 1e-5f

#define SCAN_B 1024
#define SCAN_NB ((N_NODES + SCAN_B - 1) / SCAN_B)   // 98

// ---------------- scratch (device globals; allocation-free rule) ----------------
__device__ float g_dinv[N_NODES];
__device__ int   g_cnt[N_NODES];
__device__ int   g_rowptr[N_NODES + 1];
__device__ int   g_bsum[SCAN_NB];
__device__ int   g_csr_src[N_EDGES];
__device__ float g_csr_w[N_EDGES];
__device__ float g_xa[N_NODES * IN_C];
__device__ __align__(16) float g_h1[N_NODES * HID];
__device__ __align__(16) float g_z [N_NODES * OUTF];
__device__ __align__(16) float g_h2[N_NODES * OUTF];
__device__ float g_stat1[2 * HID];
__device__ float g_stat2[2 * OUTF];
__device__ float g_sc1[HID], g_sh1[HID];
__device__ float g_sc2[OUTF], g_sh2[OUTF];
__device__ int   g_gstart[N_GRAPHS + 1];

// ---------------- helpers ----------------
__device__ __forceinline__ unsigned f2tf(float f) {
    unsigned r;
    asm("cvt.rna.tf32.f32 %0, %1;" : "=r"(r) : "f"(f));
    return r;
}
__device__ __forceinline__ void mma_tf32(float* d, const unsigned* a, const unsigned* b) {
    asm volatile(
        "mma.sync.aligned.m16n8k8.row.col.f32.tf32.tf32.f32 "
        "{%0,%1,%2,%3}, {%4,%5,%6,%7}, {%8,%9}, {%0,%1,%2,%3};"
        : "+f"(d[0]), "+f"(d[1]), "+f"(d[2]), "+f"(d[3])
        : "r"(a[0]), "r"(a[1]), "r"(a[2]), "r"(a[3]), "r"(b[0]), "r"(b[1]));
}

// ---------------- kernels ----------------

__global__ void k_init() {
    int i = blockIdx.x * blockDim.x + threadIdx.x;
    if (i < N_NODES) g_cnt[i] = 0;
    if (i < 2 * HID) g_stat1[i] = 0.f;
    if (i < 2 * OUTF) g_stat2[i] = 0.f;
}

__global__ void k_count(const int* __restrict__ edge) {
    int e = blockIdx.x * blockDim.x + threadIdx.x;
    if (e >= N_EDGES) return;
    atomicAdd(&g_cnt[edge[N_EDGES + e]], 1);
}

__global__ __launch_bounds__(SCAN_B) void k_scan1() {
    __shared__ int sh[SCAN_B];
    int t = threadIdx.x;
    int i = blockIdx.x * SCAN_B + t;
    int c = (i < N_NODES) ? g_cnt[i] : 0;
    if (i < N_NODES) g_dinv[i] = rsqrtf((float)(c + 1));
    sh[t] = c;
    __syncthreads();
#pragma unroll
    for (int off = 1; off < SCAN_B; off <<= 1) {
        int v = sh[t];
        int add = (t >= off) ? sh[t - off] : 0;
        __syncthreads();
        sh[t] = v + add;
        __syncthreads();
    }
    if (i < N_NODES) g_rowptr[i] = sh[t] - c;
    if (t == SCAN_B - 1) g_bsum[blockIdx.x] = sh[t];
}

__global__ void k_scan2() {
    __shared__ int sh[128];
    int t = threadIdx.x;
    int v = (t < SCAN_NB) ? g_bsum[t] : 0;
    sh[t] = v;
    __syncthreads();
#pragma unroll
    for (int off = 1; off < 128; off <<= 1) {
        int x = sh[t];
        int add = (t >= off) ? sh[t - off] : 0;
        __syncthreads();
        sh[t] = x + add;
        __syncthreads();
    }
    if (t < SCAN_NB) g_bsum[t] = sh[t] - v;
}

__global__ __launch_bounds__(SCAN_B) void k_scan3() {
    int i = blockIdx.x * SCAN_B + threadIdx.x;
    if (i < N_NODES) {
        g_rowptr[i] += g_bsum[blockIdx.x];
        g_cnt[i] = 0;
    }
    if (i == 0) g_rowptr[N_NODES] = N_EDGES;
}

__global__ void k_fill(const int* __restrict__ edge) {
    int e = blockIdx.x * blockDim.x + threadIdx.x;
    if (e >= N_EDGES) return;
    int s = edge[e];
    int d = edge[N_EDGES + e];
    int p = g_rowptr[d] + atomicAdd(&g_cnt[d], 1);
    g_csr_src[p] = s;
    g_csr_w[p] = g_dinv[s];
}

__global__ void k_agg1(const float* __restrict__ x) {
    int n = blockIdx.x * blockDim.x + threadIdx.x;
    if (n >= N_NODES) return;
    float acc[IN_C];
#pragma unroll
    for (int k = 0; k < IN_C; k++) acc[k] = 0.f;
    int s = g_rowptr[n], e = g_rowptr[n + 1];
    for (int p = s; p < e; p++) {
        int sn = g_csr_src[p];
        float w = g_csr_w[p];
        const float* xr = x + (long)sn * IN_C;
#pragma unroll
        for (int k = 0; k < IN_C; k++) acc[k] += w * xr[k];
    }
    float dn = g_dinv[n];
    float d2 = dn * dn;
    const float* xn = x + (long)n * IN_C;
#pragma unroll
    for (int k = 0; k < IN_C; k++) g_xa[n * IN_C + k] = dn * acc[k] + d2 * xn[k];
}

#define G1_ROWS 64
__global__ __launch_bounds__(256) void k_gemm1(const float* __restrict__ W1,
                                               const float* __restrict__ b1) {
    __shared__ float W1s[IN_C * HID];
    __shared__ float xas[G1_ROWS * IN_C];
    int t = threadIdx.x;
    int row0 = blockIdx.x * G1_ROWS;
    for (int i = t; i < IN_C * HID; i += 256) W1s[i] = W1[i];
    for (int i = t; i < G1_ROWS * IN_C; i += 256) {
        int r = row0 + i / IN_C;
        xas[i] = (r < N_NODES) ? g_xa[(long)r * IN_C + (i % IN_C)] : 0.f;
    }
    __syncthreads();
    float b1j = b1[t];
    float sum = 0.f, sq = 0.f;
    for (int r = 0; r < G1_ROWS; r++) {
        int row = row0 + r;
        if (row >= N_NODES) break;
        float h = b1j;
#pragma unroll
        for (int k = 0; k < IN_C; k++) h += xas[r * IN_C + k] * W1s[k * HID + t];
        g_h1[(long)row * HID + t] = h;
        sum += h;
        sq += h * h;
    }
    atomicAdd(&g_stat1[t], sum);
    atomicAdd(&g_stat1[HID + t], sq);
}

__global__ void k_bn1(const float* __restrict__ g1, const float* __restrict__ be1) {
    int j = threadIdx.x;
    float mean = g_stat1[j] / (float)N_NODES;
    float var = g_stat1[HID + j] / (float)N_NODES - mean * mean;
    var = fmaxf(var, 0.f);
    float sc = rsqrtf(var + BN_EPS) * g1[j];
    g_sc1[j] = sc;
    g_sh1[j] = be1[j] - mean * sc;
}

// ---- z = relu(bn1(h1)) @ W2 via tf32 mma.sync ----
// BM=128 rows/block, 8 warps, each warp 32 rows x 64 cols (2x8 m16n8k8 atoms).
// K=256 staged in BK=32 chunks. As stride 36, Bs stride 136 -> conflict-free
// fragment loads (4*row+k resp. 8*k+g cover distinct banks).
#define TCBM 128
#define TCBK 32
#define AS_S 36
#define BS_S 136
__global__ __launch_bounds__(256) void k_gemm2(const float* __restrict__ W2) {
    __shared__ unsigned As[TCBM * AS_S];
    __shared__ unsigned Bs[TCBK * BS_S];
    __shared__ float s1s[HID], t1s[HID];
    const int t = threadIdx.x;
    const int lane = t & 31;
    const int wid = t >> 5;
    const int gid = lane >> 2;       // group id 0..7
    const int t4 = lane & 3;         // thread-in-group
    const int warp_row = (wid & 3) * 32;
    const int warp_col = (wid >> 2) * 64;
    const int row0 = blockIdx.x * TCBM;

    for (int i = t; i < HID; i += 256) { s1s[i] = g_sc1[i]; t1s[i] = g_sh1[i]; }

    float acc[2][8][4];
#pragma unroll
    for (int r = 0; r < 2; r++)
#pragma unroll
        for (int c = 0; c < 8; c++)
#pragma unroll
            for (int i = 0; i < 4; i++) acc[r][c][i] = 0.f;
    __syncthreads();

    for (int kt = 0; kt < HID / TCBK; kt++) {
        // A chunk: 128 rows x 32 cols, BN+relu, tf32-convert
#pragma unroll
        for (int it = 0; it < 4; it++) {
            int q = t + it * 256;
            int row = q >> 3;
            int col4 = (q & 7) * 4;
            int kg = kt * TCBK + col4;
            int grow = row0 + row;
            float4 v = make_float4(0.f, 0.f, 0.f, 0.f);
            if (grow < N_NODES)
                v = *reinterpret_cast<const float4*>(&g_h1[(long)grow * HID + kg]);
            As[row * AS_S + col4 + 0] = f2tf(fmaxf(v.x * s1s[kg + 0] + t1s[kg + 0], 0.f));
            As[row * AS_S + col4 + 1] = f2tf(fmaxf(v.y * s1s[kg + 1] + t1s[kg + 1], 0.f));
            As[row * AS_S + col4 + 2] = f2tf(fmaxf(v.z * s1s[kg + 2] + t1s[kg + 2], 0.f));
            As[row * AS_S + col4 + 3] = f2tf(fmaxf(v.w * s1s[kg + 3] + t1s[kg + 3], 0.f));
        }
        // B chunk: 32 x 128, tf32-convert
#pragma unroll
        for (int it = 0; it < 4; it++) {
            int q = t + it * 256;
            int kb = q >> 5;
            int col4 = (q & 31) * 4;
            float4 v = *reinterpret_cast<const float4*>(&W2[(long)(kt * TCBK + kb) * OUTF + col4]);
            Bs[kb * BS_S + col4 + 0] = f2tf(v.x);
            Bs[kb * BS_S + col4 + 1] = f2tf(v.y);
            Bs[kb * BS_S + col4 + 2] = f2tf(v.z);
            Bs[kb * BS_S + col4 + 3] = f2tf(v.w);
        }
        __syncthreads();
#pragma unroll
        for (int ks = 0; ks < TCBK / 8; ks++) {
            unsigned a[2][4], b[8][2];
#pragma unroll
            for (int r = 0; r < 2; r++) {
                int rb = (warp_row + r * 16 + gid) * AS_S + ks * 8 + t4;
                a[r][0] = As[rb];
                a[r][1] = As[rb + 8 * AS_S];
                a[r][2] = As[rb + 4];
                a[r][3] = As[rb + 8 * AS_S + 4];
            }
#pragma unroll
            for (int c = 0; c < 8; c++) {
                int cb = (ks * 8 + t4) * BS_S + warp_col + c * 8 + gid;
                b[c][0] = Bs[cb];
                b[c][1] = Bs[cb + 4 * BS_S];
            }
#pragma unroll
            for (int r = 0; r < 2; r++)
#pragma unroll
                for (int c = 0; c < 8; c++) mma_tf32(acc[r][c], a[r], b[c]);
        }
        __syncthreads();
    }

    // epilogue: write g_z
#pragma unroll
    for (int r = 0; r < 2; r++) {
        int rowA = row0 + warp_row + r * 16 + gid;
        int rowB = rowA + 8;
#pragma unroll
        for (int c = 0; c < 8; c++) {
            int col = warp_col + c * 8 + t4 * 2;
            if (rowA < N_NODES)
                *reinterpret_cast<float2*>(&g_z[(long)rowA * OUTF + col]) =
                    make_float2(acc[r][c][0], acc[r][c][1]);
            if (rowB < N_NODES)
                *reinterpret_cast<float2*>(&g_z[(long)rowB * OUTF + col]) =
                    make_float2(acc[r][c][2], acc[r][c][3]);
        }
    }
}

#define A2_NPB 8
__global__ __launch_bounds__(128) void k_agg2(const float* __restrict__ b2) {
    int j = threadIdx.x;
    int n0 = blockIdx.x * A2_NPB;
    float b2j = b2[j];
    float bs = 0.f, bq = 0.f;
#pragma unroll 1
    for (int u = 0; u < A2_NPB; u++) {
        int n = n0 + u;
        int s = g_rowptr[n], e = g_rowptr[n + 1];
        float acc = 0.f;
        for (int p = s; p < e; p++) {
            int sn = g_csr_src[p];
            float w = g_csr_w[p];
            acc += w * g_z[(long)sn * OUTF + j];
        }
        float dn = g_dinv[n];
        float val = dn * acc + dn * dn * g_z[(long)n * OUTF + j] + b2j;
        g_h2[(long)n * OUTF + j] = val;
        bs += val;
        bq += val * val;
    }
    atomicAdd(&g_stat2[j], bs);
    atomicAdd(&g_stat2[OUTF + j], bq);
}

__global__ void k_bn2(const float* __restrict__ g2, const float* __restrict__ be2) {
    int j = threadIdx.x;
    float mean = g_stat2[j] / (float)N_NODES;
    float var = g_stat2[OUTF + j] / (float)N_NODES - mean * mean;
    var = fmaxf(var, 0.f);
    float sc = rsqrtf(var + BN_EPS) * g2[j];
    g_sc2[j] = sc;
    g_sh2[j] = be2[j] - mean * sc;
}

__global__ void k_gstart(const int* __restrict__ batch) {
    int i = blockIdx.x * blockDim.x + threadIdx.x;
    if (i > N_NODES) return;
    int b = (i < N_NODES) ? batch[i] : N_GRAPHS;
    int bp = (i > 0) ? batch[i - 1] : -1;
    for (int g = bp + 1; g <= b && g <= N_GRAPHS; g++) g_gstart[g] = i;
}

__global__ __launch_bounds__(128) void k_pool(float* __restrict__ out) {
    int g = blockIdx.x;
    int j = threadIdx.x;
    int s = g_gstart[g], e = g_gstart[g + 1];
    float acc = 0.f;
    for (int i = s; i < e; i++) acc += g_h2[(long)i * OUTF + j];
    int cnt = e - s;
    float y = 0.f;
    if (cnt > 0) {
        float p = acc / (float)cnt;
        y = p * g_sc2[j] + g_sh2[j];
    }
    float v = y * y;
#pragma unroll
    for (int off = 16; off > 0; off >>= 1) v += __shfl_xor_sync(0xffffffffu, v, off);
    __shared__ float ws[4];
    if ((j & 31) == 0) ws[j >> 5] = v;
    __syncthreads();
    float ss = ws[0] + ws[1] + ws[2] + ws[3];
    float nrm = sqrtf(ss);
    out[g * OUTF + j] = y / fmaxf(nrm, 1e-12f);
}

// ---------------- launch ----------------
extern "C" void kernel_launch(void* const* d_in, const int* in_sizes, int n_in,
                              void* d_out, int out_size) {
    const float* x   = (const float*)d_in[0];
    const float* W1  = (const float*)d_in[1];
    const float* b1  = (const float*)d_in[2];
    const float* g1  = (const float*)d_in[3];
    const float* be1 = (const float*)d_in[4];
    const float* W2  = (const float*)d_in[5];
    const float* b2  = (const float*)d_in[6];
    const float* g2  = (const float*)d_in[7];
    const float* be2 = (const float*)d_in[8];
    const int* edge  = (const int*)d_in[9];
    const int* batch = (const int*)d_in[10];
    float* out = (float*)d_out;

    const int TB = 256;
    int nb_N = (N_NODES + TB - 1) / TB;
    int nb_E = (N_EDGES + TB - 1) / TB;

    k_init<<<nb_N, TB>>>();
    k_count<<<nb_E, TB>>>(edge);
    k_scan1<<<SCAN_NB, SCAN_B>>>();
    k_scan2<<<1, 128>>>();
    k_scan3<<<SCAN_NB, SCAN_B>>>();
    k_fill<<<nb_E, TB>>>(edge);
    k_agg1<<<nb_N, TB>>>(x);
    k_gemm1<<<(N_NODES + G1_ROWS - 1) / G1_ROWS, 256>>>(W1, b1);
    k_bn1<<<1, HID>>>(g1, be1);
    k_gemm2<<<(N_NODES + TCBM - 1) / TCBM, 256>>>(W2);
    k_agg2<<<N_NODES / A2_NPB, 128>>>(b2);
    k_bn2<<<1, OUTF>>>(g2, be2);
    k_gstart<<<(N_NODES + 1 + TB - 1) / TB, TB>>>(batch);
    k_pool<<<N_GRAPHS, 128>>>(out);
}